// round 1
// baseline (speedup 1.0000x reference)
#include <cuda_runtime.h>
#include <cuda_bf16.h>
#include <math.h>

#define N_NODES 100000
#define N_EDGES 1000000
#define N_GRAPHS 4096
#define F_IN 9
#define H 64

// ---------------- device scratch (no allocation allowed) ----------------
__device__ int   g_is64;                    // 1 if edge_index/batch are int64
__device__ int   g_deg[N_NODES];            // degree incl. self-loop
__device__ int   g_off[N_NODES];            // exclusive prefix of deg (CSR offsets by dst)
__device__ int   g_cur[N_NODES];            // per-node fill cursor (also = #real edges)
__device__ float g_dis[N_NODES];            // rsqrt(deg)
__device__ int   g_csr[N_NODES + N_EDGES];  // src ids grouped by dst
__device__ float g_tmp[(size_t)N_NODES * H]; // GEMM output (pre-aggregation)
__device__ float g_h[(size_t)N_NODES * H];   // layer output (post relu)
__device__ float g_pool[(size_t)N_GRAPHS * H];
__device__ float g_cnt[N_GRAPHS];

__device__ __forceinline__ long long load_idx(const void* p, long long i, int is64) {
    if (is64) return ((const long long*)p)[i];
    return (long long)((const int*)p)[i];
}

// ---------------- dtype detection: int64 stores have zero high words ----
__global__ void k_detect(const void* ei) {
    const int* p = (const int*)ei;
    int all0 = 1;
    #pragma unroll
    for (int k = 0; k < 32; k++)
        if (p[2 * k + 1] != 0) all0 = 0;
    g_is64 = all0;
}

// ---------------- init: deg=1 (self loop), cursors, pool accumulators ---
__global__ void k_init() {
    int i = blockIdx.x * blockDim.x + threadIdx.x;
    if (i < N_NODES) { g_deg[i] = 1; g_cur[i] = 0; }
    if (i < N_GRAPHS * H) g_pool[i] = 0.f;
    if (i < N_GRAPHS) g_cnt[i] = 0.f;
}

// ---------------- degree count over dst ---------------------------------
__global__ void k_count(const void* ei) {
    int i = blockIdx.x * blockDim.x + threadIdx.x;
    if (i >= N_EDGES) return;
    int is64 = g_is64;
    int d = (int)load_idx(ei, (long long)N_EDGES + i, is64);
    atomicAdd(&g_deg[d], 1);
}

// ---------------- single-block exclusive scan + dis ---------------------
__global__ void k_scan() {
    __shared__ int ssum[1024];
    int tid = threadIdx.x;
    const int CH = (N_NODES + 1023) / 1024;
    int start = tid * CH;
    int end = min(start + CH, N_NODES);
    int s = 0;
    for (int i = start; i < end; i++) s += g_deg[i];
    ssum[tid] = s;
    __syncthreads();
    // Hillis-Steele inclusive scan
    for (int d = 1; d < 1024; d <<= 1) {
        int v = (tid >= d) ? ssum[tid - d] : 0;
        __syncthreads();
        ssum[tid] += v;
        __syncthreads();
    }
    int run = ssum[tid] - s;  // exclusive prefix for this chunk
    for (int i = start; i < end; i++) {
        g_off[i] = run;
        run += g_deg[i];
        g_dis[i] = rsqrtf((float)g_deg[i]);
    }
}

// ---------------- CSR fill (counting sort by dst) ------------------------
__global__ void k_fill(const void* ei) {
    int i = blockIdx.x * blockDim.x + threadIdx.x;
    if (i >= N_EDGES) return;
    int is64 = g_is64;
    int s = (int)load_idx(ei, i, is64);
    int d = (int)load_idx(ei, (long long)N_EDGES + i, is64);
    int p = atomicAdd(&g_cur[d], 1);
    g_csr[g_off[d] + p] = s;
}

// ---------------- tiled GEMM: out[N,64] = in[N,K] @ W[K,64] -------------
template <int K>
__global__ void k_gemm(const float* __restrict__ in, const float* __restrict__ W,
                       float* __restrict__ out) {
    __shared__ float sW[K * 64];
    __shared__ float sH[32 * K];
    int tid = threadIdx.x;
    int r0 = blockIdx.x * 32;
    for (int i = tid; i < K * 64; i += 256) sW[i] = W[i];
    for (int i = tid; i < 32 * K; i += 256) {
        int r = r0 + i / K;
        sH[i] = (r < N_NODES) ? in[(size_t)r * K + (i % K)] : 0.f;
    }
    __syncthreads();
    int c = tid & 63;
    int rg = tid >> 6;
    #pragma unroll
    for (int rr = rg; rr < 32; rr += 4) {
        int r = r0 + rr;
        if (r >= N_NODES) continue;
        float acc = 0.f;
        #pragma unroll
        for (int k = 0; k < K; k++) acc = fmaf(sH[rr * K + k], sW[k * 64 + c], acc);
        out[(size_t)r * 64 + c] = acc;
    }
}

// ---------------- aggregation: one warp per node -------------------------
__global__ void k_agg(const float* __restrict__ hin, const float* __restrict__ bias,
                      float* __restrict__ hout) {
    int warp = threadIdx.x >> 5;
    int lane = threadIdx.x & 31;
    int v = blockIdx.x * 4 + warp;
    if (v >= N_NODES) return;
    float dv = g_dis[v];
    const float* row = hin + (size_t)v * 64;
    float a0 = dv * row[lane];
    float a1 = dv * row[lane + 32];
    int st = g_off[v];
    int cnt = g_cur[v];
    for (int e = 0; e < cnt; e++) {
        int s = g_csr[st + e];
        float ds = g_dis[s];
        const float* rs = hin + (size_t)s * 64;
        a0 = fmaf(ds, rs[lane], a0);
        a1 = fmaf(ds, rs[lane + 32], a1);
    }
    float o0 = fmaf(dv, a0, bias[lane]);
    float o1 = fmaf(dv, a1, bias[lane + 32]);
    hout[(size_t)v * 64 + lane] = fmaxf(o0, 0.f);
    hout[(size_t)v * 64 + lane + 32] = fmaxf(o1, 0.f);
}

// ---------------- pooling: atomic accumulate per graph -------------------
__global__ void k_pool(const float* __restrict__ h, const void* batch) {
    int warp = threadIdx.x >> 5;
    int lane = threadIdx.x & 31;
    int v = blockIdx.x * 4 + warp;
    if (v >= N_NODES) return;
    int is64 = g_is64;
    int g = (int)load_idx(batch, v, is64);
    atomicAdd(&g_pool[(size_t)g * 64 + lane], h[(size_t)v * 64 + lane]);
    atomicAdd(&g_pool[(size_t)g * 64 + lane + 32], h[(size_t)v * 64 + lane + 32]);
    if (lane == 0) atomicAdd(&g_cnt[g], 1.f);
}

// ---------------- final: mean + linear head ------------------------------
__global__ void k_final(const float* __restrict__ Wout, const float* __restrict__ bout,
                        float* __restrict__ out) {
    int warp = threadIdx.x >> 5;
    int lane = threadIdx.x & 31;
    int g = blockIdx.x * 4 + warp;
    if (g >= N_GRAPHS) return;
    float inv = 1.f / fmaxf(g_cnt[g], 1.f);
    float s = g_pool[(size_t)g * 64 + lane] * Wout[lane] +
              g_pool[(size_t)g * 64 + lane + 32] * Wout[lane + 32];
    #pragma unroll
    for (int o = 16; o > 0; o >>= 1) s += __shfl_down_sync(0xffffffffu, s, o);
    if (lane == 0) out[g] = s * inv + bout[0];
}

// ---------------- launch --------------------------------------------------
extern "C" void kernel_launch(void* const* d_in, const int* in_sizes, int n_in,
                              void* d_out, int out_size) {
    const float* x     = (const float*)d_in[0];
    const void*  ei    = d_in[1];
    const void*  batch = d_in[2];
    const float* W1 = (const float*)d_in[3];
    const float* b1 = (const float*)d_in[4];
    const float* W2 = (const float*)d_in[5];
    const float* b2 = (const float*)d_in[6];
    const float* W3 = (const float*)d_in[7];
    const float* b3 = (const float*)d_in[8];
    const float* W4 = (const float*)d_in[9];
    const float* b4 = (const float*)d_in[10];
    const float* Wout = (const float*)d_in[11];
    const float* bout = (const float*)d_in[12];
    float* out = (float*)d_out;

    float* tmp; cudaGetSymbolAddress((void**)&tmp, g_tmp);
    float* h;   cudaGetSymbolAddress((void**)&h, g_h);

    k_detect<<<1, 1>>>(ei);

    int init_n = (N_GRAPHS * H > N_NODES) ? N_GRAPHS * H : N_NODES;
    k_init<<<(init_n + 255) / 256, 256>>>();

    k_count<<<(N_EDGES + 255) / 256, 256>>>(ei);
    k_scan<<<1, 1024>>>();
    k_fill<<<(N_EDGES + 255) / 256, 256>>>(ei);

    const int gemm_blocks = (N_NODES + 31) / 32;
    const int agg_blocks = (N_NODES + 3) / 4;

    // layer 1
    k_gemm<F_IN><<<gemm_blocks, 256>>>(x, W1, tmp);
    k_agg<<<agg_blocks, 128>>>(tmp, b1, h);
    // layer 2
    k_gemm<H><<<gemm_blocks, 256>>>(h, W2, tmp);
    k_agg<<<agg_blocks, 128>>>(tmp, b2, h);
    // layer 3
    k_gemm<H><<<gemm_blocks, 256>>>(h, W3, tmp);
    k_agg<<<agg_blocks, 128>>>(tmp, b3, h);
    // layer 4
    k_gemm<H><<<gemm_blocks, 256>>>(h, W4, tmp);
    k_agg<<<agg_blocks, 128>>>(tmp, b4, h);

    // pool + head
    k_pool<<<agg_blocks, 128>>>(h, batch);
    k_final<<<(N_GRAPHS + 3) / 4, 128>>>(Wout, bout, out);
}

// round 2
// speedup vs baseline: 1.3839x; 1.3839x over previous
#include <cuda_runtime.h>
#include <cuda_bf16.h>
#include <math.h>

#define N_NODES 100000
#define N_EDGES 1000000
#define N_GRAPHS 4096
#define F_IN 9
#define H 64
#define SCAN_BLK 1024
#define N_SBLK ((N_NODES + SCAN_BLK - 1) / SCAN_BLK)  // 98

// ---------------- device scratch (no allocation allowed) ----------------
__device__ int   g_is64;
__device__ int   g_deg[N_NODES];
__device__ int   g_off[N_NODES];
__device__ int   g_cur[N_NODES];
__device__ float g_dis[N_NODES];
__device__ int   g_bsum[N_SBLK];
__device__ int   g_csr[N_NODES + N_EDGES];
__device__ float g_tmp[(size_t)N_NODES * H];
__device__ float g_h[(size_t)N_NODES * H];
__device__ float g_pool[(size_t)N_GRAPHS * H];
__device__ float g_cnt[N_GRAPHS];

__device__ __forceinline__ long long load_idx(const void* p, long long i, int is64) {
    if (is64) return ((const long long*)p)[i];
    return (long long)((const int*)p)[i];
}

// ---------------- dtype detection -----------------------------------------
__global__ void k_detect(const void* ei) {
    const int* p = (const int*)ei;
    int all0 = 1;
    #pragma unroll
    for (int k = 0; k < 32; k++)
        if (p[2 * k + 1] != 0) all0 = 0;
    g_is64 = all0;
}

// ---------------- init ------------------------------------------------------
__global__ void k_init() {
    int i = blockIdx.x * blockDim.x + threadIdx.x;
    if (i < N_NODES) { g_deg[i] = 1; g_cur[i] = 0; }
    if (i < N_GRAPHS * H) g_pool[i] = 0.f;
    if (i < N_GRAPHS) g_cnt[i] = 0.f;
}

// ---------------- degree count over dst -------------------------------------
__global__ void k_count(const void* ei) {
    int i = blockIdx.x * blockDim.x + threadIdx.x;
    if (i >= N_EDGES) return;
    int is64 = g_is64;
    int d = (int)load_idx(ei, (long long)N_EDGES + i, is64);
    atomicAdd(&g_deg[d], 1);
}

// ---------------- multi-block scan: phase 1 (block sums) --------------------
__global__ void k_bsum() {
    int i = blockIdx.x * SCAN_BLK + threadIdx.x;
    int d = (i < N_NODES) ? g_deg[i] : 0;
    #pragma unroll
    for (int o = 16; o > 0; o >>= 1) d += __shfl_down_sync(0xffffffffu, d, o);
    __shared__ int ws[32];
    if ((threadIdx.x & 31) == 0) ws[threadIdx.x >> 5] = d;
    __syncthreads();
    if (threadIdx.x < 32) {
        int v = ws[threadIdx.x];
        #pragma unroll
        for (int o = 16; o > 0; o >>= 1) v += __shfl_down_sync(0xffffffffu, v, o);
        if (threadIdx.x == 0) g_bsum[blockIdx.x] = v;
    }
}

// ---------------- phase 2: scan of 98 block sums (1 block) ------------------
__global__ void k_bscan() {
    __shared__ int s[128];
    int t = threadIdx.x;
    int v = (t < N_SBLK) ? g_bsum[t] : 0;
    s[t] = v;
    __syncthreads();
    for (int d = 1; d < 128; d <<= 1) {
        int u = (t >= d) ? s[t - d] : 0;
        __syncthreads();
        s[t] += u;
        __syncthreads();
    }
    if (t < N_SBLK) g_bsum[t] = s[t] - v;  // exclusive
}

// ---------------- phase 3: block-local scan + offsets + dis -----------------
__global__ void k_off() {
    int i = blockIdx.x * SCAN_BLK + threadIdx.x;
    int d = (i < N_NODES) ? g_deg[i] : 0;
    int lane = threadIdx.x & 31, w = threadIdx.x >> 5;
    int inc = d;
    #pragma unroll
    for (int o = 1; o < 32; o <<= 1) {
        int u = __shfl_up_sync(0xffffffffu, inc, o);
        if (lane >= o) inc += u;
    }
    __shared__ int ws[32];
    if (lane == 31) ws[w] = inc;
    __syncthreads();
    if (w == 0) {
        int v = ws[lane];
        int inc2 = v;
        #pragma unroll
        for (int o = 1; o < 32; o <<= 1) {
            int u = __shfl_up_sync(0xffffffffu, inc2, o);
            if (lane >= o) inc2 += u;
        }
        ws[lane] = inc2 - v;  // exclusive warp offset
    }
    __syncthreads();
    if (i < N_NODES) {
        g_off[i] = g_bsum[blockIdx.x] + ws[w] + inc - d;
        g_dis[i] = rsqrtf((float)d);
    }
}

// ---------------- CSR fill ---------------------------------------------------
__global__ void k_fill(const void* ei) {
    int i = blockIdx.x * blockDim.x + threadIdx.x;
    if (i >= N_EDGES) return;
    int is64 = g_is64;
    int s = (int)load_idx(ei, i, is64);
    int d = (int)load_idx(ei, (long long)N_EDGES + i, is64);
    int p = atomicAdd(&g_cur[d], 1);
    g_csr[g_off[d] + p] = s;
}

// ---------------- tiled GEMM: out[N,64] = in[N,K] @ W[K,64] -----------------
template <int K>
__global__ void k_gemm(const float* __restrict__ in, const float* __restrict__ W,
                       float* __restrict__ out) {
    __shared__ float sW[K * 64];
    __shared__ float sH[32 * K];
    int tid = threadIdx.x;
    int r0 = blockIdx.x * 32;
    for (int i = tid; i < K * 64; i += 256) sW[i] = W[i];
    for (int i = tid; i < 32 * K; i += 256) {
        int r = r0 + i / K;
        sH[i] = (r < N_NODES) ? in[(size_t)r * K + (i % K)] : 0.f;
    }
    __syncthreads();
    int c = tid & 63;
    int rg = tid >> 6;
    #pragma unroll
    for (int rr = rg; rr < 32; rr += 4) {
        int r = r0 + rr;
        if (r >= N_NODES) continue;
        float acc = 0.f;
        #pragma unroll
        for (int k = 0; k < K; k++) acc = fmaf(sH[rr * K + k], sW[k * 64 + c], acc);
        out[(size_t)r * 64 + c] = acc;
    }
}

// ---------------- aggregation: one warp per node, warp-tiled CSR ------------
__global__ void k_agg(const float* __restrict__ hin, const float* __restrict__ bias,
                      float* __restrict__ hout) {
    int warp = threadIdx.x >> 5;
    int lane = threadIdx.x & 31;
    int v = blockIdx.x * 4 + warp;
    if (v >= N_NODES) return;
    float dv = g_dis[v];
    float2 self = ((const float2*)(hin + (size_t)v * 64))[lane];
    float a0 = dv * self.x;
    float a1 = dv * self.y;
    int st = g_off[v];
    int cnt = g_cur[v];
    for (int base = 0; base < cnt; base += 32) {
        int e = base + lane;
        int s = 0;
        float ds = 0.f;
        if (e < cnt) {
            s = g_csr[st + e];
            ds = g_dis[s];
        }
        int m = min(32, cnt - base);
        for (int j = 0; j < m; j++) {
            int sj = __shfl_sync(0xffffffffu, s, j);
            float dsj = __shfl_sync(0xffffffffu, ds, j);
            float2 val = ((const float2*)(hin + (size_t)sj * 64))[lane];
            a0 = fmaf(dsj, val.x, a0);
            a1 = fmaf(dsj, val.y, a1);
        }
    }
    float2 b = ((const float2*)bias)[lane];
    float2 o;
    o.x = fmaxf(fmaf(dv, a0, b.x), 0.f);
    o.y = fmaxf(fmaf(dv, a1, b.y), 0.f);
    ((float2*)(hout + (size_t)v * 64))[lane] = o;
}

// ---------------- pooling -----------------------------------------------------
__global__ void k_pool(const float* __restrict__ h, const void* batch) {
    int warp = threadIdx.x >> 5;
    int lane = threadIdx.x & 31;
    int v = blockIdx.x * 4 + warp;
    if (v >= N_NODES) return;
    int is64 = g_is64;
    int g = (int)load_idx(batch, v, is64);
    float2 val = ((const float2*)(h + (size_t)v * 64))[lane];
    atomicAdd(&g_pool[(size_t)g * 64 + 2 * lane], val.x);
    atomicAdd(&g_pool[(size_t)g * 64 + 2 * lane + 1], val.y);
    if (lane == 0) atomicAdd(&g_cnt[g], 1.f);
}

// ---------------- final: mean + linear head ----------------------------------
__global__ void k_final(const float* __restrict__ Wout, const float* __restrict__ bout,
                        float* __restrict__ out) {
    int warp = threadIdx.x >> 5;
    int lane = threadIdx.x & 31;
    int g = blockIdx.x * 4 + warp;
    if (g >= N_GRAPHS) return;
    float inv = 1.f / fmaxf(g_cnt[g], 1.f);
    float s = g_pool[(size_t)g * 64 + lane] * Wout[lane] +
              g_pool[(size_t)g * 64 + lane + 32] * Wout[lane + 32];
    #pragma unroll
    for (int o = 16; o > 0; o >>= 1) s += __shfl_down_sync(0xffffffffu, s, o);
    if (lane == 0) out[g] = s * inv + bout[0];
}

// ---------------- launch -------------------------------------------------------
extern "C" void kernel_launch(void* const* d_in, const int* in_sizes, int n_in,
                              void* d_out, int out_size) {
    const float* x     = (const float*)d_in[0];
    const void*  ei    = d_in[1];
    const void*  batch = d_in[2];
    const float* W1 = (const float*)d_in[3];
    const float* b1 = (const float*)d_in[4];
    const float* W2 = (const float*)d_in[5];
    const float* b2 = (const float*)d_in[6];
    const float* W3 = (const float*)d_in[7];
    const float* b3 = (const float*)d_in[8];
    const float* W4 = (const float*)d_in[9];
    const float* b4 = (const float*)d_in[10];
    const float* Wout = (const float*)d_in[11];
    const float* bout = (const float*)d_in[12];
    float* out = (float*)d_out;

    float* tmp; cudaGetSymbolAddress((void**)&tmp, g_tmp);
    float* h;   cudaGetSymbolAddress((void**)&h, g_h);

    k_detect<<<1, 1>>>(ei);

    int init_n = (N_GRAPHS * H > N_NODES) ? N_GRAPHS * H : N_NODES;
    k_init<<<(init_n + 255) / 256, 256>>>();

    k_count<<<(N_EDGES + 255) / 256, 256>>>(ei);
    k_bsum<<<N_SBLK, SCAN_BLK>>>();
    k_bscan<<<1, 128>>>();
    k_off<<<N_SBLK, SCAN_BLK>>>();
    k_fill<<<(N_EDGES + 255) / 256, 256>>>(ei);

    const int gemm_blocks = (N_NODES + 31) / 32;
    const int agg_blocks = (N_NODES + 3) / 4;

    k_gemm<F_IN><<<gemm_blocks, 256>>>(x, W1, tmp);
    k_agg<<<agg_blocks, 128>>>(tmp, b1, h);
    k_gemm<H><<<gemm_blocks, 256>>>(h, W2, tmp);
    k_agg<<<agg_blocks, 128>>>(tmp, b2, h);
    k_gemm<H><<<gemm_blocks, 256>>>(h, W3, tmp);
    k_agg<<<agg_blocks, 128>>>(tmp, b3, h);
    k_gemm<H><<<gemm_blocks, 256>>>(h, W4, tmp);
    k_agg<<<agg_blocks, 128>>>(tmp, b4, h);

    k_pool<<<agg_blocks, 128>>>(h, batch);
    k_final<<<(N_GRAPHS + 3) / 4, 128>>>(Wout, bout, out);
}

// round 3
// speedup vs baseline: 2.4019x; 1.7355x over previous
#include <cuda_runtime.h>
#include <cuda_bf16.h>
#include <math.h>

#define N_NODES 100000
#define N_EDGES 1000000
#define N_GRAPHS 4096
#define F_IN 9
#define H 64
#define SCAN_BLK 1024
#define N_SBLK ((N_NODES + SCAN_BLK - 1) / SCAN_BLK)  // 98

// ---------------- device scratch ----------------
__device__ int   g_is64;
__device__ int   g_deg[N_NODES];
__device__ int   g_off[N_NODES];
__device__ int   g_cur[N_NODES];
__device__ float g_dis[N_NODES];
__device__ int   g_bsum[N_SBLK];
__device__ int   g_csr[N_NODES + N_EDGES];
__device__ float g_xa[(size_t)N_NODES * F_IN];   // aggregated input features
__device__ float g_tmp[(size_t)N_NODES * H];     // aggregated hidden (pre-GEMM)
__device__ float g_h[(size_t)N_NODES * H];       // post GEMM+ReLU hidden
__device__ float g_pool[(size_t)N_GRAPHS * H];
__device__ float g_cnt[N_GRAPHS];

__device__ __forceinline__ long long load_idx(const void* p, long long i, int is64) {
    if (is64) return ((const long long*)p)[i];
    return (long long)((const int*)p)[i];
}

// ---------------- dtype detection ----------------
__global__ void k_detect(const void* ei) {
    const int* p = (const int*)ei;
    int all0 = 1;
    #pragma unroll
    for (int k = 0; k < 32; k++)
        if (p[2 * k + 1] != 0) all0 = 0;
    g_is64 = all0;
}

// ---------------- init ----------------
__global__ void k_init() {
    int i = blockIdx.x * blockDim.x + threadIdx.x;
    if (i < N_NODES) { g_deg[i] = 1; g_cur[i] = 0; }
    if (i < N_GRAPHS * H) g_pool[i] = 0.f;
    if (i < N_GRAPHS) g_cnt[i] = 0.f;
}

// ---------------- degree count ----------------
__global__ void k_count(const void* ei) {
    int i = blockIdx.x * blockDim.x + threadIdx.x;
    if (i >= N_EDGES) return;
    int d = (int)load_idx(ei, (long long)N_EDGES + i, g_is64);
    atomicAdd(&g_deg[d], 1);
}

// ---------------- multi-block scan ----------------
__global__ void k_bsum() {
    int i = blockIdx.x * SCAN_BLK + threadIdx.x;
    int d = (i < N_NODES) ? g_deg[i] : 0;
    #pragma unroll
    for (int o = 16; o > 0; o >>= 1) d += __shfl_down_sync(0xffffffffu, d, o);
    __shared__ int ws[32];
    if ((threadIdx.x & 31) == 0) ws[threadIdx.x >> 5] = d;
    __syncthreads();
    if (threadIdx.x < 32) {
        int v = ws[threadIdx.x];
        #pragma unroll
        for (int o = 16; o > 0; o >>= 1) v += __shfl_down_sync(0xffffffffu, v, o);
        if (threadIdx.x == 0) g_bsum[blockIdx.x] = v;
    }
}

__global__ void k_bscan() {
    __shared__ int s[128];
    int t = threadIdx.x;
    int v = (t < N_SBLK) ? g_bsum[t] : 0;
    s[t] = v;
    __syncthreads();
    for (int d = 1; d < 128; d <<= 1) {
        int u = (t >= d) ? s[t - d] : 0;
        __syncthreads();
        s[t] += u;
        __syncthreads();
    }
    if (t < N_SBLK) g_bsum[t] = s[t] - v;
}

__global__ void k_off() {
    int i = blockIdx.x * SCAN_BLK + threadIdx.x;
    int d = (i < N_NODES) ? g_deg[i] : 0;
    int lane = threadIdx.x & 31, w = threadIdx.x >> 5;
    int inc = d;
    #pragma unroll
    for (int o = 1; o < 32; o <<= 1) {
        int u = __shfl_up_sync(0xffffffffu, inc, o);
        if (lane >= o) inc += u;
    }
    __shared__ int ws[32];
    if (lane == 31) ws[w] = inc;
    __syncthreads();
    if (w == 0) {
        int v = ws[lane];
        int inc2 = v;
        #pragma unroll
        for (int o = 1; o < 32; o <<= 1) {
            int u = __shfl_up_sync(0xffffffffu, inc2, o);
            if (lane >= o) inc2 += u;
        }
        ws[lane] = inc2 - v;
    }
    __syncthreads();
    if (i < N_NODES) {
        g_off[i] = g_bsum[blockIdx.x] + ws[w] + inc - d;
        g_dis[i] = rsqrtf((float)d);
    }
}

// ---------------- CSR fill ----------------
__global__ void k_fill(const void* ei) {
    int i = blockIdx.x * blockDim.x + threadIdx.x;
    if (i >= N_EDGES) return;
    int is64 = g_is64;
    int s = (int)load_idx(ei, i, is64);
    int d = (int)load_idx(ei, (long long)N_EDGES + i, is64);
    int p = atomicAdd(&g_cur[d], 1);
    g_csr[g_off[d] + p] = s;
}

// ---------------- layer-1 aggregation on raw 9-wide input -----------------
// thread = (node, col); also accumulates per-graph node counts (col==0).
__global__ void k_agg9(const float* __restrict__ x, const void* batch) {
    int t = blockIdx.x * blockDim.x + threadIdx.x;
    if (t >= N_NODES * F_IN) return;
    int v = t / F_IN;
    int c = t - v * F_IN;
    float dv = g_dis[v];
    float acc = x[(size_t)v * F_IN + c];
    int st = g_off[v];
    int cnt = g_cur[v];
    acc *= dv;
    for (int e = 0; e < cnt; e++) {
        int s = g_csr[st + e];
        acc = fmaf(g_dis[s], x[(size_t)s * F_IN + c], acc);
    }
    g_xa[(size_t)v * F_IN + c] = dv * acc;
    if (c == 0) {
        int g = (int)load_idx(batch, v, g_is64);
        atomicAdd(&g_cnt[g], 1.f);
    }
}

// ---------------- aggregation on 64-wide hidden: warp per node ------------
__global__ void k_agg64(const float* __restrict__ hin, float* __restrict__ hout) {
    int warp = threadIdx.x >> 5;
    int lane = threadIdx.x & 31;
    int v = blockIdx.x * 4 + warp;
    if (v >= N_NODES) return;
    float dv = g_dis[v];
    float2 self = ((const float2*)(hin + (size_t)v * 64))[lane];
    float a0 = dv * self.x;
    float a1 = dv * self.y;
    int st = g_off[v];
    int cnt = g_cur[v];
    for (int base = 0; base < cnt; base += 32) {
        int e = base + lane;
        int s = 0;
        float ds = 0.f;
        if (e < cnt) {
            s = g_csr[st + e];
            ds = g_dis[s];
        }
        int m = min(32, cnt - base);
        for (int j = 0; j < m; j++) {
            int sj = __shfl_sync(0xffffffffu, s, j);
            float dsj = __shfl_sync(0xffffffffu, ds, j);
            float2 val = ((const float2*)(hin + (size_t)sj * 64))[lane];
            a0 = fmaf(dsj, val.x, a0);
            a1 = fmaf(dsj, val.y, a1);
        }
    }
    float2 o;
    o.x = dv * a0;
    o.y = dv * a1;
    ((float2*)(hout + (size_t)v * 64))[lane] = o;
}

// ---------------- register-tiled GEMM: out = relu(in[N,K] @ W[K,64] + b) --
// MODE 0: write out[N,64]. MODE 1: atomicAdd relu result into g_pool (no out).
// Block: 128 rows; 256 threads; thread tile 8 rows x 4 cols.
// dynamic smem: sHT[K][132] (transposed input) + sW[K][64].
template <int K, int MODE>
__global__ void __launch_bounds__(256)
k_gemmT(const float* __restrict__ in, const float* __restrict__ W,
        const float* __restrict__ bias, float* __restrict__ out,
        const void* batch) {
    extern __shared__ float sm[];
    float* sHT = sm;            // [K][132]
    float* sW = sm + K * 132;   // [K][64]
    __shared__ int sB[128];

    int tid = threadIdx.x;
    int rblk = blockIdx.x * 128;

    for (int i = tid; i < K * 16; i += 256)
        ((float4*)sW)[i] = ((const float4*)W)[i];

    if (K == 64) {
        for (int i = tid; i < 128 * 16; i += 256) {
            int r = i >> 4, k4 = i & 15;
            float4 v = make_float4(0.f, 0.f, 0.f, 0.f);
            if (rblk + r < N_NODES)
                v = ((const float4*)in)[(size_t)(rblk + r) * 16 + k4];
            sHT[(4 * k4 + 0) * 132 + r] = v.x;
            sHT[(4 * k4 + 1) * 132 + r] = v.y;
            sHT[(4 * k4 + 2) * 132 + r] = v.z;
            sHT[(4 * k4 + 3) * 132 + r] = v.w;
        }
    } else {
        for (int i = tid; i < 128 * K; i += 256) {
            int r = i / K, k = i - r * K;
            float v = (rblk + r < N_NODES) ? in[(size_t)(rblk + r) * K + k] : 0.f;
            sHT[k * 132 + r] = v;
        }
    }
    if (MODE == 1 && tid < 128)
        sB[tid] = (rblk + tid < N_NODES) ? (int)load_idx(batch, rblk + tid, g_is64) : 0;
    __syncthreads();

    int cg = tid & 15, rg = tid >> 4;
    int c0 = cg * 4, r0 = rg * 8;

    float4 acc[8];
    #pragma unroll
    for (int j = 0; j < 8; j++) acc[j] = make_float4(0.f, 0.f, 0.f, 0.f);

    #pragma unroll 8
    for (int k = 0; k < K; k++) {
        float4 w = *(const float4*)(sW + k * 64 + c0);
        float4 h0 = *(const float4*)(sHT + k * 132 + r0);
        float4 h1 = *(const float4*)(sHT + k * 132 + r0 + 4);
        float hv[8] = {h0.x, h0.y, h0.z, h0.w, h1.x, h1.y, h1.z, h1.w};
        #pragma unroll
        for (int j = 0; j < 8; j++) {
            acc[j].x = fmaf(hv[j], w.x, acc[j].x);
            acc[j].y = fmaf(hv[j], w.y, acc[j].y);
            acc[j].z = fmaf(hv[j], w.z, acc[j].z);
            acc[j].w = fmaf(hv[j], w.w, acc[j].w);
        }
    }

    float4 b = *(const float4*)(bias + c0);
    #pragma unroll
    for (int j = 0; j < 8; j++) {
        int row = rblk + r0 + j;
        if (row >= N_NODES) continue;
        float4 o;
        o.x = fmaxf(acc[j].x + b.x, 0.f);
        o.y = fmaxf(acc[j].y + b.y, 0.f);
        o.z = fmaxf(acc[j].z + b.z, 0.f);
        o.w = fmaxf(acc[j].w + b.w, 0.f);
        if (MODE == 0) {
            *(float4*)(out + (size_t)row * 64 + c0) = o;
        } else {
            int g = sB[r0 + j];
            atomicAdd(&g_pool[(size_t)g * 64 + c0 + 0], o.x);
            atomicAdd(&g_pool[(size_t)g * 64 + c0 + 1], o.y);
            atomicAdd(&g_pool[(size_t)g * 64 + c0 + 2], o.z);
            atomicAdd(&g_pool[(size_t)g * 64 + c0 + 3], o.w);
        }
    }
}

// ---------------- final: mean + linear head ----------------
__global__ void k_final(const float* __restrict__ Wout, const float* __restrict__ bout,
                        float* __restrict__ out) {
    int warp = threadIdx.x >> 5;
    int lane = threadIdx.x & 31;
    int g = blockIdx.x * 4 + warp;
    if (g >= N_GRAPHS) return;
    float inv = 1.f / fmaxf(g_cnt[g], 1.f);
    float s = g_pool[(size_t)g * 64 + lane] * Wout[lane] +
              g_pool[(size_t)g * 64 + lane + 32] * Wout[lane + 32];
    #pragma unroll
    for (int o = 16; o > 0; o >>= 1) s += __shfl_down_sync(0xffffffffu, s, o);
    if (lane == 0) out[g] = s * inv + bout[0];
}

// ---------------- launch ----------------
extern "C" void kernel_launch(void* const* d_in, const int* in_sizes, int n_in,
                              void* d_out, int out_size) {
    const float* x     = (const float*)d_in[0];
    const void*  ei    = d_in[1];
    const void*  batch = d_in[2];
    const float* W1 = (const float*)d_in[3];
    const float* b1 = (const float*)d_in[4];
    const float* W2 = (const float*)d_in[5];
    const float* b2 = (const float*)d_in[6];
    const float* W3 = (const float*)d_in[7];
    const float* b3 = (const float*)d_in[8];
    const float* W4 = (const float*)d_in[9];
    const float* b4 = (const float*)d_in[10];
    const float* Wout = (const float*)d_in[11];
    const float* bout = (const float*)d_in[12];
    float* out = (float*)d_out;

    float* xa;  cudaGetSymbolAddress((void**)&xa, g_xa);
    float* tmp; cudaGetSymbolAddress((void**)&tmp, g_tmp);
    float* h;   cudaGetSymbolAddress((void**)&h, g_h);

    const int smem64 = 64 * 132 * 4 + 64 * 64 * 4;  // 50176
    const int smem9  = F_IN * 132 * 4 + F_IN * 64 * 4;
    static int attr_done = 0;
    if (!attr_done) {
        cudaFuncSetAttribute((const void*)k_gemmT<64, 0>,
                             cudaFuncAttributeMaxDynamicSharedMemorySize, smem64);
        cudaFuncSetAttribute((const void*)k_gemmT<64, 1>,
                             cudaFuncAttributeMaxDynamicSharedMemorySize, smem64);
        attr_done = 1;
    }

    k_detect<<<1, 1>>>(ei);
    int init_n = (N_GRAPHS * H > N_NODES) ? N_GRAPHS * H : N_NODES;
    k_init<<<(init_n + 255) / 256, 256>>>();

    k_count<<<(N_EDGES + 255) / 256, 256>>>(ei);
    k_bsum<<<N_SBLK, SCAN_BLK>>>();
    k_bscan<<<1, 128>>>();
    k_off<<<N_SBLK, SCAN_BLK>>>();
    k_fill<<<(N_EDGES + 255) / 256, 256>>>(ei);

    const int agg_blocks  = (N_NODES + 3) / 4;
    const int gemm_blocks = (N_NODES + 127) / 128;

    // layer 1: agg(x) -> xa ; h = relu(xa @ W1 + b1)
    k_agg9<<<(N_NODES * F_IN + 255) / 256, 256>>>(x, batch);
    k_gemmT<F_IN, 0><<<gemm_blocks, 256, smem9>>>(xa, W1, b1, h, batch);
    // layer 2
    k_agg64<<<agg_blocks, 128>>>(h, tmp);
    k_gemmT<64, 0><<<gemm_blocks, 256, smem64>>>(tmp, W2, b2, h, batch);
    // layer 3
    k_agg64<<<agg_blocks, 128>>>(h, tmp);
    k_gemmT<64, 0><<<gemm_blocks, 256, smem64>>>(tmp, W3, b3, h, batch);
    // layer 4: GEMM epilogue pools directly
    k_agg64<<<agg_blocks, 128>>>(h, tmp);
    k_gemmT<64, 1><<<gemm_blocks, 256, smem64>>>(tmp, W4, b4, nullptr, batch);

    k_final<<<(N_GRAPHS + 3) / 4, 128>>>(Wout, bout, out);
}

// round 4
// speedup vs baseline: 2.7109x; 1.1287x over previous
#include <cuda_runtime.h>
#include <cuda_fp16.h>
#include <math.h>

#define N_NODES 100000
#define N_EDGES 1000000
#define N_GRAPHS 4096
#define F_IN 9
#define H 64
#define SCAN_BLK 1024
#define N_SBLK ((N_NODES + SCAN_BLK - 1) / SCAN_BLK)  // 98
#define N_PAD (N_NODES + 128)                          // pad for 128-row GEMM tiles

// ---------------- device scratch ----------------
__device__ int     g_is64;
__device__ int     g_deg[N_NODES];
__device__ int     g_off[N_NODES];
__device__ int     g_cur[N_NODES];
__device__ float   g_dis[N_NODES];
__device__ int     g_bsum[N_SBLK];
__device__ int     g_csr[N_NODES + N_EDGES];
__device__ float   g_xa[(size_t)N_NODES * F_IN];   // aggregated input features (fp32)
__device__ __half2 g_h16[(size_t)N_PAD * 32];      // hidden activations (fp16)
__device__ __half2 g_t16[(size_t)N_PAD * 32];      // aggregated hidden (fp16)
__device__ uint2   g_wpk[3][1024];                 // fragment-packed fp16 weights W2..W4
__device__ float   g_pool[(size_t)N_GRAPHS * H];
__device__ float   g_cnt[N_GRAPHS];

__device__ __forceinline__ long long load_idx(const void* p, long long i, int is64) {
    if (is64) return ((const long long*)p)[i];
    return (long long)((const int*)p)[i];
}

// ---------------- dtype detection ----------------
__global__ void k_detect(const void* ei) {
    const int* p = (const int*)ei;
    int all0 = 1;
    #pragma unroll
    for (int k = 0; k < 32; k++)
        if (p[2 * k + 1] != 0) all0 = 0;
    g_is64 = all0;
}

// ---------------- init ----------------
__global__ void k_init() {
    int i = blockIdx.x * blockDim.x + threadIdx.x;
    if (i < N_NODES) { g_deg[i] = 1; g_cur[i] = 0; }
    if (i < N_GRAPHS * H) g_pool[i] = 0.f;
    if (i < N_GRAPHS) g_cnt[i] = 0.f;
}

// ---------------- degree count ----------------
__global__ void k_count(const void* ei) {
    int i = blockIdx.x * blockDim.x + threadIdx.x;
    if (i >= N_EDGES) return;
    int d = (int)load_idx(ei, (long long)N_EDGES + i, g_is64);
    atomicAdd(&g_deg[d], 1);
}

// ---------------- multi-block scan ----------------
__global__ void k_bsum() {
    int i = blockIdx.x * SCAN_BLK + threadIdx.x;
    int d = (i < N_NODES) ? g_deg[i] : 0;
    #pragma unroll
    for (int o = 16; o > 0; o >>= 1) d += __shfl_down_sync(0xffffffffu, d, o);
    __shared__ int ws[32];
    if ((threadIdx.x & 31) == 0) ws[threadIdx.x >> 5] = d;
    __syncthreads();
    if (threadIdx.x < 32) {
        int v = ws[threadIdx.x];
        #pragma unroll
        for (int o = 16; o > 0; o >>= 1) v += __shfl_down_sync(0xffffffffu, v, o);
        if (threadIdx.x == 0) g_bsum[blockIdx.x] = v;
    }
}

__global__ void k_bscan() {
    __shared__ int s[128];
    int t = threadIdx.x;
    int v = (t < N_SBLK) ? g_bsum[t] : 0;
    s[t] = v;
    __syncthreads();
    for (int d = 1; d < 128; d <<= 1) {
        int u = (t >= d) ? s[t - d] : 0;
        __syncthreads();
        s[t] += u;
        __syncthreads();
    }
    if (t < N_SBLK) g_bsum[t] = s[t] - v;
}

__global__ void k_off() {
    int i = blockIdx.x * SCAN_BLK + threadIdx.x;
    int d = (i < N_NODES) ? g_deg[i] : 0;
    int lane = threadIdx.x & 31, w = threadIdx.x >> 5;
    int inc = d;
    #pragma unroll
    for (int o = 1; o < 32; o <<= 1) {
        int u = __shfl_up_sync(0xffffffffu, inc, o);
        if (lane >= o) inc += u;
    }
    __shared__ int ws[32];
    if (lane == 31) ws[w] = inc;
    __syncthreads();
    if (w == 0) {
        int v = ws[lane];
        int inc2 = v;
        #pragma unroll
        for (int o = 1; o < 32; o <<= 1) {
            int u = __shfl_up_sync(0xffffffffu, inc2, o);
            if (lane >= o) inc2 += u;
        }
        ws[lane] = inc2 - v;
    }
    __syncthreads();
    if (i < N_NODES) {
        g_off[i] = g_bsum[blockIdx.x] + ws[w] + inc - d;
        g_dis[i] = rsqrtf((float)d);
    }
}

// ---------------- CSR fill ----------------
__global__ void k_fill(const void* ei) {
    int i = blockIdx.x * blockDim.x + threadIdx.x;
    if (i >= N_EDGES) return;
    int is64 = g_is64;
    int s = (int)load_idx(ei, i, is64);
    int d = (int)load_idx(ei, (long long)N_EDGES + i, is64);
    int p = atomicAdd(&g_cur[d], 1);
    g_csr[g_off[d] + p] = s;
}

// ---------------- pack W2..W4 into mma B-fragment order ----------------
// layout: wpk[layer][(ks*8+nt)*32 + lane] = {b0,b1} (uint2 of half2)
// b0 = {W[16ks+2t][8nt+g], W[16ks+2t+1][8nt+g]}, b1 = rows +8,+9
__global__ void k_packW(const float* __restrict__ W2, const float* __restrict__ W3,
                        const float* __restrict__ W4) {
    int id = blockIdx.x * 256 + threadIdx.x;
    if (id >= 3 * 1024) return;
    const float* W = (id < 1024) ? W2 : ((id < 2048) ? W3 : W4);
    int idx = id & 1023;
    int ks = idx >> 8, nt = (idx >> 5) & 7, l = idx & 31;
    int g = l >> 2, t = l & 3;
    int n = nt * 8 + g;
    int k0 = ks * 16 + 2 * t;
    __half2 b0 = __floats2half2_rn(W[k0 * 64 + n], W[(k0 + 1) * 64 + n]);
    __half2 b1 = __floats2half2_rn(W[(k0 + 8) * 64 + n], W[(k0 + 9) * 64 + n]);
    uint2 u;
    u.x = *reinterpret_cast<unsigned*>(&b0);
    u.y = *reinterpret_cast<unsigned*>(&b1);
    g_wpk[id >> 10][idx] = u;
}

// ---------------- layer-1 aggregation on raw 9-wide input ----------------
__global__ void k_agg9(const float* __restrict__ x, const void* batch) {
    int t = blockIdx.x * blockDim.x + threadIdx.x;
    if (t >= N_NODES * F_IN) return;
    int v = t / F_IN;
    int c = t - v * F_IN;
    float dv = g_dis[v];
    float acc = x[(size_t)v * F_IN + c];
    int st = g_off[v];
    int cnt = g_cur[v];
    acc *= dv;
    for (int e = 0; e < cnt; e++) {
        int s = g_csr[st + e];
        acc = fmaf(g_dis[s], x[(size_t)s * F_IN + c], acc);
    }
    g_xa[(size_t)v * F_IN + c] = dv * acc;
    if (c == 0) {
        int g = (int)load_idx(batch, v, g_is64);
        atomicAdd(&g_cnt[g], 1.f);
    }
}

// ---------------- layer-1 GEMM (K=9, FFMA): h16 = relu(xa @ W1 + b1) -----
__global__ void __launch_bounds__(256)
k_gemm9(const float* __restrict__ in, const float* __restrict__ W,
        const float* __restrict__ bias, __half2* __restrict__ out) {
    __shared__ float sHT[F_IN * 132];
    __shared__ float sW[F_IN * 64];
    int tid = threadIdx.x;
    int rblk = blockIdx.x * 128;
    for (int i = tid; i < F_IN * 64; i += 256) sW[i] = W[i];
    for (int i = tid; i < 128 * F_IN; i += 256) {
        int r = i / F_IN, k = i - r * F_IN;
        sHT[k * 132 + r] = (rblk + r < N_NODES) ? in[(size_t)(rblk + r) * F_IN + k] : 0.f;
    }
    __syncthreads();
    int cg = tid & 15, rg = tid >> 4;
    int c0 = cg * 4, r0 = rg * 8;
    float4 acc[8];
    #pragma unroll
    for (int j = 0; j < 8; j++) acc[j] = make_float4(0.f, 0.f, 0.f, 0.f);
    #pragma unroll
    for (int k = 0; k < F_IN; k++) {
        float4 w = *(const float4*)(sW + k * 64 + c0);
        float4 h0 = *(const float4*)(sHT + k * 132 + r0);
        float4 h1 = *(const float4*)(sHT + k * 132 + r0 + 4);
        float hv[8] = {h0.x, h0.y, h0.z, h0.w, h1.x, h1.y, h1.z, h1.w};
        #pragma unroll
        for (int j = 0; j < 8; j++) {
            acc[j].x = fmaf(hv[j], w.x, acc[j].x);
            acc[j].y = fmaf(hv[j], w.y, acc[j].y);
            acc[j].z = fmaf(hv[j], w.z, acc[j].z);
            acc[j].w = fmaf(hv[j], w.w, acc[j].w);
        }
    }
    float4 b = *(const float4*)(bias + c0);
    #pragma unroll
    for (int j = 0; j < 8; j++) {
        int row = rblk + r0 + j;
        if (row >= N_NODES) continue;
        float ox = fmaxf(acc[j].x + b.x, 0.f);
        float oy = fmaxf(acc[j].y + b.y, 0.f);
        float oz = fmaxf(acc[j].z + b.z, 0.f);
        float ow = fmaxf(acc[j].w + b.w, 0.f);
        out[(size_t)row * 32 + cg * 2 + 0] = __floats2half2_rn(ox, oy);
        out[(size_t)row * 32 + cg * 2 + 1] = __floats2half2_rn(oz, ow);
    }
}

// ---------------- fp16 aggregation: warp per node -------------------------
__global__ void k_agg64h(const __half2* __restrict__ hin, __half2* __restrict__ hout) {
    int warp = threadIdx.x >> 5;
    int lane = threadIdx.x & 31;
    int v = blockIdx.x * 4 + warp;
    if (v >= N_NODES) return;
    float dv = g_dis[v];
    float2 sf = __half22float2(hin[(size_t)v * 32 + lane]);
    float a0 = dv * sf.x;
    float a1 = dv * sf.y;
    int st = g_off[v];
    int cnt = g_cur[v];
    for (int base = 0; base < cnt; base += 32) {
        int e = base + lane;
        int s = 0;
        float ds = 0.f;
        if (e < cnt) {
            s = g_csr[st + e];
            ds = g_dis[s];
        }
        int m = min(32, cnt - base);
        for (int j = 0; j < m; j++) {
            int sj = __shfl_sync(0xffffffffu, s, j);
            float dsj = __shfl_sync(0xffffffffu, ds, j);
            float2 vf = __half22float2(hin[(size_t)sj * 32 + lane]);
            a0 = fmaf(dsj, vf.x, a0);
            a1 = fmaf(dsj, vf.y, a1);
        }
    }
    hout[(size_t)v * 32 + lane] = __floats2half2_rn(dv * a0, dv * a1);
}

// ---------------- tensor-core GEMM: out = relu(A[N,64]@W[64,64] + b) ------
// A fp16 (half2 as uint, row stride 32), W pre-packed fragments, fp32 accum.
// MODE 0: write fp16 out. MODE 1: atomicAdd relu result into g_pool.
template <int MODE>
__global__ void __launch_bounds__(256)
k_hgemm(const unsigned* __restrict__ A, const uint2* __restrict__ Wpk,
        const float* __restrict__ bias, __half2* __restrict__ out,
        const void* batch) {
    int w = threadIdx.x >> 5, l = threadIdx.x & 31;
    int g = l >> 2, t = l & 3;
    int row0 = blockIdx.x * 128 + w * 16;
    int ra = row0 + g, rb = row0 + g + 8;

    float acc[8][4];
    #pragma unroll
    for (int i = 0; i < 8; i++) {
        acc[i][0] = acc[i][1] = acc[i][2] = acc[i][3] = 0.f;
    }

    #pragma unroll
    for (int ks = 0; ks < 4; ks++) {
        unsigned a0 = A[(size_t)ra * 32 + ks * 8 + t];
        unsigned a1 = A[(size_t)rb * 32 + ks * 8 + t];
        unsigned a2 = A[(size_t)ra * 32 + ks * 8 + t + 4];
        unsigned a3 = A[(size_t)rb * 32 + ks * 8 + t + 4];
        #pragma unroll
        for (int nt = 0; nt < 8; nt++) {
            uint2 b = Wpk[(ks * 8 + nt) * 32 + l];
            asm volatile(
                "mma.sync.aligned.m16n8k16.row.col.f32.f16.f16.f32 "
                "{%0,%1,%2,%3}, {%4,%5,%6,%7}, {%8,%9}, {%0,%1,%2,%3};"
                : "+f"(acc[nt][0]), "+f"(acc[nt][1]),
                  "+f"(acc[nt][2]), "+f"(acc[nt][3])
                : "r"(a0), "r"(a1), "r"(a2), "r"(a3), "r"(b.x), "r"(b.y));
        }
    }

    int ga = 0, gb = 0;
    if (MODE == 1) {
        int is64 = g_is64;
        ga = (int)load_idx(batch, min(ra, N_NODES - 1), is64);
        gb = (int)load_idx(batch, min(rb, N_NODES - 1), is64);
    }
    #pragma unroll
    for (int nt = 0; nt < 8; nt++) {
        float2 bv = ((const float2*)bias)[nt * 4 + t];
        float o0 = fmaxf(acc[nt][0] + bv.x, 0.f);
        float o1 = fmaxf(acc[nt][1] + bv.y, 0.f);
        float o2 = fmaxf(acc[nt][2] + bv.x, 0.f);
        float o3 = fmaxf(acc[nt][3] + bv.y, 0.f);
        if (MODE == 0) {
            out[(size_t)ra * 32 + nt * 4 + t] = __floats2half2_rn(o0, o1);
            out[(size_t)rb * 32 + nt * 4 + t] = __floats2half2_rn(o2, o3);
        } else {
            if (ra < N_NODES) {
                atomicAdd(&g_pool[(size_t)ga * 64 + nt * 8 + 2 * t + 0], o0);
                atomicAdd(&g_pool[(size_t)ga * 64 + nt * 8 + 2 * t + 1], o1);
            }
            if (rb < N_NODES) {
                atomicAdd(&g_pool[(size_t)gb * 64 + nt * 8 + 2 * t + 0], o2);
                atomicAdd(&g_pool[(size_t)gb * 64 + nt * 8 + 2 * t + 1], o3);
            }
        }
    }
}

// ---------------- final: mean + linear head ----------------
__global__ void k_final(const float* __restrict__ Wout, const float* __restrict__ bout,
                        float* __restrict__ out) {
    int warp = threadIdx.x >> 5;
    int lane = threadIdx.x & 31;
    int g = blockIdx.x * 4 + warp;
    if (g >= N_GRAPHS) return;
    float inv = 1.f / fmaxf(g_cnt[g], 1.f);
    float s = g_pool[(size_t)g * 64 + lane] * Wout[lane] +
              g_pool[(size_t)g * 64 + lane + 32] * Wout[lane + 32];
    #pragma unroll
    for (int o = 16; o > 0; o >>= 1) s += __shfl_down_sync(0xffffffffu, s, o);
    if (lane == 0) out[g] = s * inv + bout[0];
}

// ---------------- launch ----------------
extern "C" void kernel_launch(void* const* d_in, const int* in_sizes, int n_in,
                              void* d_out, int out_size) {
    const float* x     = (const float*)d_in[0];
    const void*  ei    = d_in[1];
    const void*  batch = d_in[2];
    const float* W1 = (const float*)d_in[3];
    const float* b1 = (const float*)d_in[4];
    const float* W2 = (const float*)d_in[5];
    const float* b2 = (const float*)d_in[6];
    const float* W3 = (const float*)d_in[7];
    const float* b3 = (const float*)d_in[8];
    const float* W4 = (const float*)d_in[9];
    const float* b4 = (const float*)d_in[10];
    const float* Wout = (const float*)d_in[11];
    const float* bout = (const float*)d_in[12];
    float* out = (float*)d_out;

    float*   xa;  cudaGetSymbolAddress((void**)&xa, g_xa);
    __half2* h16; cudaGetSymbolAddress((void**)&h16, g_h16);
    __half2* t16; cudaGetSymbolAddress((void**)&t16, g_t16);
    uint2*   wpk; cudaGetSymbolAddress((void**)&wpk, g_wpk);

    k_detect<<<1, 1>>>(ei);
    int init_n = (N_GRAPHS * H > N_NODES) ? N_GRAPHS * H : N_NODES;
    k_init<<<(init_n + 255) / 256, 256>>>();

    k_count<<<(N_EDGES + 255) / 256, 256>>>(ei);
    k_bsum<<<N_SBLK, SCAN_BLK>>>();
    k_bscan<<<1, 128>>>();
    k_off<<<N_SBLK, SCAN_BLK>>>();
    k_fill<<<(N_EDGES + 255) / 256, 256>>>(ei);
    k_packW<<<12, 256>>>(W2, W3, W4);

    const int agg_blocks  = (N_NODES + 3) / 4;
    const int gemm_blocks = (N_NODES + 127) / 128;

    // layer 1
    k_agg9<<<(N_NODES * F_IN + 255) / 256, 256>>>(x, batch);
    k_gemm9<<<gemm_blocks, 256>>>(xa, W1, b1, h16);
    // layer 2
    k_agg64h<<<agg_blocks, 128>>>(h16, t16);
    k_hgemm<0><<<gemm_blocks, 256>>>((const unsigned*)t16, wpk + 0 * 1024, b2, h16, batch);
    // layer 3
    k_agg64h<<<agg_blocks, 128>>>(h16, t16);
    k_hgemm<0><<<gemm_blocks, 256>>>((const unsigned*)t16, wpk + 1 * 1024, b3, h16, batch);
    // layer 4: GEMM epilogue pools directly
    k_agg64h<<<agg_blocks, 128>>>(h16, t16);
    k_hgemm<1><<<gemm_blocks, 256>>>((const unsigned*)t16, wpk + 2 * 1024, b4, nullptr, batch);

    k_final<<<(N_GRAPHS + 3) / 4, 128>>>(Wout, bout, out);
}